// round 1
// baseline (speedup 1.0000x reference)
#include <cuda_runtime.h>
#include <cuda_bf16.h>

// Problem constants
#define BB   8
#define TT   512
#define CC   1024
#define NHH  16
#define DHH  64
#define HWW  256
#define MM   (BB*TT)          // 4096 rows for projections

// Scratch (device globals; no allocation allowed)
__device__ float g_q[BB*NHH*TT*DHH];   // [b,h,t,d]
__device__ float g_k[BB*NHH*TT*DHH];
__device__ float g_v[BB*NHH*TT*DHH];
__device__ float g_y[MM*CC];           // attention output, flat [m, c]

// ---------------------------------------------------------------------------
// GEMM: out[m,n] = sum_k A[m,k] * W[n,k] + bias[n]
// M=4096, N=1024, K=1024. BM=BN=128, BK=16, 256 threads, 8x8 per thread.
// heads!=0 -> write in [b,h,t,d] layout; else flat [m,n].
// ---------------------------------------------------------------------------
__global__ __launch_bounds__(256) void gemm128(const float* __restrict__ A,
                                               const float* __restrict__ W,
                                               const float* __restrict__ bias,
                                               float* __restrict__ out,
                                               int heads) {
    __shared__ float As[16][132];   // [k][m], padded
    __shared__ float Bs[16][132];   // [k][n], padded

    const int lt  = threadIdx.x;
    const int tx  = lt & 15;        // 0..15 -> 8 cols each
    const int ty  = lt >> 4;        // 0..15 -> 8 rows each
    const int row0 = blockIdx.y * 128;
    const int col0 = blockIdx.x * 128;

    const int l_row = lt >> 1;          // 0..127
    const int l_k   = (lt & 1) * 8;     // 0 or 8

    const float* Ap = A + (size_t)(row0 + l_row) * CC + l_k;
    const float* Wp = W + (size_t)(col0 + l_row) * CC + l_k;

    float acc[8][8];
    #pragma unroll
    for (int i = 0; i < 8; i++)
        #pragma unroll
        for (int j = 0; j < 8; j++) acc[i][j] = 0.f;

    for (int k0 = 0; k0 < CC; k0 += 16) {
        float4 a0 = *(const float4*)(Ap + k0);
        float4 a1 = *(const float4*)(Ap + k0 + 4);
        float4 w0 = *(const float4*)(Wp + k0);
        float4 w1 = *(const float4*)(Wp + k0 + 4);

        As[l_k+0][l_row] = a0.x; As[l_k+1][l_row] = a0.y;
        As[l_k+2][l_row] = a0.z; As[l_k+3][l_row] = a0.w;
        As[l_k+4][l_row] = a1.x; As[l_k+5][l_row] = a1.y;
        As[l_k+6][l_row] = a1.z; As[l_k+7][l_row] = a1.w;
        Bs[l_k+0][l_row] = w0.x; Bs[l_k+1][l_row] = w0.y;
        Bs[l_k+2][l_row] = w0.z; Bs[l_k+3][l_row] = w0.w;
        Bs[l_k+4][l_row] = w1.x; Bs[l_k+5][l_row] = w1.y;
        Bs[l_k+6][l_row] = w1.z; Bs[l_k+7][l_row] = w1.w;
        __syncthreads();

        #pragma unroll
        for (int kk = 0; kk < 16; kk++) {
            float4 ra0 = *(const float4*)&As[kk][ty*8];
            float4 ra1 = *(const float4*)&As[kk][ty*8+4];
            float4 rb0 = *(const float4*)&Bs[kk][tx*8];
            float4 rb1 = *(const float4*)&Bs[kk][tx*8+4];
            float ra[8] = {ra0.x, ra0.y, ra0.z, ra0.w, ra1.x, ra1.y, ra1.z, ra1.w};
            float rb[8] = {rb0.x, rb0.y, rb0.z, rb0.w, rb1.x, rb1.y, rb1.z, rb1.w};
            #pragma unroll
            for (int i = 0; i < 8; i++)
                #pragma unroll
                for (int j = 0; j < 8; j++)
                    acc[i][j] += ra[i] * rb[j];
        }
        __syncthreads();
    }

    #pragma unroll
    for (int i = 0; i < 8; i++) {
        int m = row0 + ty*8 + i;
        int bb = m >> 9;          // batch
        int t  = m & 511;         // token
        #pragma unroll
        for (int j = 0; j < 8; j++) {
            int n = col0 + tx*8 + j;
            float v = acc[i][j] + bias[n];
            if (heads) {
                int h = n >> 6, d = n & 63;
                out[(size_t)(((bb*NHH + h)*TT) + t)*DHH + d] = v;
            } else {
                out[(size_t)m*CC + n] = v;
            }
        }
    }
}

// ---------------------------------------------------------------------------
// Attention: per block = one (b,h) pair, 8 q-rows. Scores -> mask -> softmax
// -> P@V, all in SMEM. 256 threads = 8 warps, warp r owns q-row r.
// ---------------------------------------------------------------------------
__global__ __launch_bounds__(256) void attn_kernel(const float* __restrict__ fwd,
                                                   const float* __restrict__ bwd) {
    __shared__ float Qs[8][64];
    __shared__ float S[8][512];
    __shared__ float KV[64][65];

    const int bh = blockIdx.x;         // 0..127
    const int b  = bh >> 4;
    const int h  = bh & 15;
    const int q0 = blockIdx.y * 8;
    const int lt = threadIdx.x;
    const int r    = lt >> 5;
    const int lane = lt & 31;
    const int qglob = q0 + r;

    const float* qbase = g_q + (size_t)(bh*TT + q0)*DHH;
    const float* kbase = g_k + (size_t)bh*TT*DHH;
    const float* vbase = g_v + (size_t)bh*TT*DHH;

    // load 8x64 Q tile
    for (int e = lt; e < 512; e += 256) Qs[e >> 6][e & 63] = qbase[e];

    // ---- scores: S[r][k] = 0.125 * q.k (masked) ----
    for (int kc = 0; kc < 8; kc++) {
        __syncthreads();
        for (int e = lt; e < 4096; e += 256)
            KV[e >> 6][e & 63] = kbase[kc*4096 + e];
        __syncthreads();

        float a0 = 0.f, a1 = 0.f;
        #pragma unroll
        for (int d = 0; d < 64; d++) {
            float qv = Qs[r][d];
            a0 += qv * KV[lane][d];
            a1 += qv * KV[lane + 32][d];
        }
        a0 *= 0.125f; a1 *= 0.125f;

        int kg0 = kc*64 + lane, kg1 = kg0 + 32;
        if (qglob < HWW) {
            const float* fr = fwd + (size_t)(b*HWW + qglob)*HWW;
            const float* br = bwd + (size_t)b*HWW*HWW;
            if (kg0 < HWW) a0 *= fr[kg0] * br[kg0*HWW + qglob];
            if (kg1 < HWW) a1 *= fr[kg1] * br[kg1*HWW + qglob];
        }
        S[r][kg0] = a0;
        S[r][kg1] = a1;
    }

    // ---- softmax over 512 (warp r owns row r; S rows are warp-private) ----
    {
        float vals[16];
        float mx = -1e30f;
        #pragma unroll
        for (int i = 0; i < 16; i++) {
            vals[i] = S[r][i*32 + lane];
            mx = fmaxf(mx, vals[i]);
        }
        #pragma unroll
        for (int o = 16; o > 0; o >>= 1)
            mx = fmaxf(mx, __shfl_xor_sync(0xffffffffu, mx, o));
        float sum = 0.f;
        #pragma unroll
        for (int i = 0; i < 16; i++) {
            vals[i] = __expf(vals[i] - mx);
            sum += vals[i];
        }
        #pragma unroll
        for (int o = 16; o > 0; o >>= 1)
            sum += __shfl_xor_sync(0xffffffffu, sum, o);
        float inv = 1.f / sum;
        #pragma unroll
        for (int i = 0; i < 16; i++)
            S[r][i*32 + lane] = vals[i] * inv;
    }

    // ---- O = P @ V ----
    float o0 = 0.f, o1 = 0.f;
    const int d0 = lane, d1 = lane + 32;
    for (int kc = 0; kc < 8; kc++) {
        __syncthreads();
        for (int e = lt; e < 4096; e += 256)
            KV[e >> 6][e & 63] = vbase[kc*4096 + e];
        __syncthreads();

        #pragma unroll
        for (int j = 0; j < 64; j++) {
            float p = S[r][kc*64 + j];
            o0 += p * KV[j][d0];
            o1 += p * KV[j][d1];
        }
    }

    float* yb = g_y + (size_t)(b*TT + qglob)*CC + h*DHH;
    yb[d0] = o0;
    yb[d1] = o1;
}

// ---------------------------------------------------------------------------
extern "C" void kernel_launch(void* const* d_in, const int* in_sizes, int n_in,
                              void* d_out, int out_size) {
    const float* x    = (const float*)d_in[0];
    const float* src  = (const float*)d_in[1];
    const float* fwd  = (const float*)d_in[2];
    const float* bwd  = (const float*)d_in[3];
    const float* Wq   = (const float*)d_in[4];
    const float* bq   = (const float*)d_in[5];
    const float* Wk   = (const float*)d_in[6];
    const float* bk   = (const float*)d_in[7];
    const float* Wv   = (const float*)d_in[8];
    const float* bv   = (const float*)d_in[9];
    const float* Wp   = (const float*)d_in[10];
    const float* bp   = (const float*)d_in[11];
    float* out = (float*)d_out;

    float *pq, *pk, *pv, *py;
    cudaGetSymbolAddress((void**)&pq, g_q);
    cudaGetSymbolAddress((void**)&pk, g_k);
    cudaGetSymbolAddress((void**)&pv, g_v);
    cudaGetSymbolAddress((void**)&py, g_y);

    dim3 ggrid(CC/128, MM/128);      // (8, 32)
    gemm128<<<ggrid, 256>>>(x,   Wq, bq, pq, 1);
    gemm128<<<ggrid, 256>>>(src, Wk, bk, pk, 1);
    gemm128<<<ggrid, 256>>>(src, Wv, bv, pv, 1);

    dim3 agrid(BB*NHH, TT/8);        // (128, 64)
    attn_kernel<<<agrid, 256>>>(fwd, bwd);

    gemm128<<<ggrid, 256>>>(py, Wp, bp, out, 0);
}

// round 3
// speedup vs baseline: 1.4100x; 1.4100x over previous
#include <cuda_runtime.h>
#include <cuda_bf16.h>

#define BB   8
#define TT   512
#define CC   1024
#define NHH  16
#define DHH  64
#define HWW  256
#define MM   (BB*TT)

// Scratch
__device__ float g_q [BB*NHH*TT*DHH];   // [bh][t][d]
__device__ float g_k [BB*NHH*TT*DHH];
__device__ float g_v [BB*NHH*TT*DHH];
__device__ float g_qT[BB*NHH*DHH*TT];   // [bh][d][t]
__device__ float g_kT[BB*NHH*DHH*TT];
__device__ float g_mask[BB*HWW*HWW];    // [b][q][k] = fwd[q][k]*bwd[k][q]
__device__ float g_y [MM*CC];

// ---------------------------------------------------------------------------
// Projection GEMM: out[m,n] = sum_k A[m,k]*W[n,k] + bias[n]
// ---------------------------------------------------------------------------
__global__ __launch_bounds__(256) void gemm128(const float* __restrict__ A,
                                               const float* __restrict__ W,
                                               const float* __restrict__ bias,
                                               float* __restrict__ out,
                                               int heads) {
    __shared__ float As[16][132];
    __shared__ float Bs[16][132];

    const int lt  = threadIdx.x;
    const int tx  = lt & 15;
    const int ty  = lt >> 4;
    const int row0 = blockIdx.y * 128;
    const int col0 = blockIdx.x * 128;

    const int l_row = lt >> 1;
    const int l_k   = (lt & 1) * 8;

    const float* Ap = A + (size_t)(row0 + l_row) * CC + l_k;
    const float* Wp = W + (size_t)(col0 + l_row) * CC + l_k;

    float acc[8][8];
    #pragma unroll
    for (int i = 0; i < 8; i++)
        #pragma unroll
        for (int j = 0; j < 8; j++) acc[i][j] = 0.f;

    for (int k0 = 0; k0 < CC; k0 += 16) {
        float4 a0 = *(const float4*)(Ap + k0);
        float4 a1 = *(const float4*)(Ap + k0 + 4);
        float4 w0 = *(const float4*)(Wp + k0);
        float4 w1 = *(const float4*)(Wp + k0 + 4);

        As[l_k+0][l_row] = a0.x; As[l_k+1][l_row] = a0.y;
        As[l_k+2][l_row] = a0.z; As[l_k+3][l_row] = a0.w;
        As[l_k+4][l_row] = a1.x; As[l_k+5][l_row] = a1.y;
        As[l_k+6][l_row] = a1.z; As[l_k+7][l_row] = a1.w;
        Bs[l_k+0][l_row] = w0.x; Bs[l_k+1][l_row] = w0.y;
        Bs[l_k+2][l_row] = w0.z; Bs[l_k+3][l_row] = w0.w;
        Bs[l_k+4][l_row] = w1.x; Bs[l_k+5][l_row] = w1.y;
        Bs[l_k+6][l_row] = w1.z; Bs[l_k+7][l_row] = w1.w;
        __syncthreads();

        #pragma unroll
        for (int kk = 0; kk < 16; kk++) {
            float4 ra0 = *(const float4*)&As[kk][ty*8];
            float4 ra1 = *(const float4*)&As[kk][ty*8+4];
            float4 rb0 = *(const float4*)&Bs[kk][tx*8];
            float4 rb1 = *(const float4*)&Bs[kk][tx*8+4];
            float ra[8] = {ra0.x, ra0.y, ra0.z, ra0.w, ra1.x, ra1.y, ra1.z, ra1.w};
            float rb[8] = {rb0.x, rb0.y, rb0.z, rb0.w, rb1.x, rb1.y, rb1.z, rb1.w};
            #pragma unroll
            for (int i = 0; i < 8; i++)
                #pragma unroll
                for (int j = 0; j < 8; j++)
                    acc[i][j] += ra[i] * rb[j];
        }
        __syncthreads();
    }

    #pragma unroll
    for (int i = 0; i < 8; i++) {
        int m = row0 + ty*8 + i;
        int bb = m >> 9;
        int t  = m & 511;
        #pragma unroll
        for (int j = 0; j < 8; j++) {
            int n = col0 + tx*8 + j;
            float v = acc[i][j] + bias[n];
            if (heads) {
                int h = n >> 6, d = n & 63;
                out[(size_t)(((bb*NHH + h)*TT) + t)*DHH + d] = v;
            } else {
                out[(size_t)m*CC + n] = v;
            }
        }
    }
}

// ---------------------------------------------------------------------------
// Transpose [bh][t=512][d=64] -> [bh][d=64][t=512]
// ---------------------------------------------------------------------------
__global__ void trans_td(const float* __restrict__ in, float* __restrict__ out) {
    __shared__ float tile[32][33];
    const int bh = blockIdx.z;
    const int d0 = blockIdx.x * 32, t0 = blockIdx.y * 32;
    const float* ip = in  + (size_t)bh*TT*DHH;
    float*       op = out + (size_t)bh*DHH*TT;
    const int tx = threadIdx.x, ty = threadIdx.y;
    #pragma unroll
    for (int i = 0; i < 32; i += 8)
        tile[ty+i][tx] = ip[(size_t)(t0+ty+i)*DHH + d0 + tx];
    __syncthreads();
    #pragma unroll
    for (int i = 0; i < 32; i += 8)
        op[(size_t)(d0+ty+i)*TT + t0 + tx] = tile[tx][ty+i];
}

// ---------------------------------------------------------------------------
// mask[b][q][k] = fwd[b][q][k] * bwd[b][k][q]
// ---------------------------------------------------------------------------
__global__ void mask_prod(const float* __restrict__ fwd,
                          const float* __restrict__ bwd,
                          float* __restrict__ out) {
    __shared__ float tile[32][33];
    const int b  = blockIdx.z;
    const int x0 = blockIdx.x * 32, y0 = blockIdx.y * 32;
    const float* fp = fwd + (size_t)b*HWW*HWW;
    const float* bp = bwd + (size_t)b*HWW*HWW;
    float*       op = out + (size_t)b*HWW*HWW;
    const int tx = threadIdx.x, ty = threadIdx.y;
    #pragma unroll
    for (int i = 0; i < 32; i += 8)
        tile[ty+i][tx] = bp[(size_t)(y0+ty+i)*HWW + x0 + tx];
    __syncthreads();
    #pragma unroll
    for (int i = 0; i < 32; i += 8) {
        int q = x0 + ty + i;
        int k = y0 + tx;
        op[(size_t)q*HWW + k] = fp[(size_t)q*HWW + k] * tile[tx][ty+i];
    }
}

// ---------------------------------------------------------------------------
// Attention v2: block = (b,h) x 64 q-rows. S[64][512] in smem.
//   S-phase: 8x8 microtile from transposed Q/K  (64 FMA / 4 LDS.128)
//   softmax: warp per 8 rows
//   PV-phase: 4x4 microtile, k-unroll 4         (64 FMA / 8 LDS.128)
// Dynamic smem: S 64*516 + Qt 64*68 + KV 64*260 = 54016 floats = 216064 B
// ---------------------------------------------------------------------------
#define S_PAD  516
#define QT_OFF 33024
#define KV_OFF 37376
#define ATTN_SMEM (54016*4)

extern __shared__ float sm_attn[];

__global__ __launch_bounds__(256, 1) void attn2(const float* __restrict__ qT,
                                                const float* __restrict__ kT,
                                                const float* __restrict__ v,
                                                const float* __restrict__ maskp,
                                                float* __restrict__ y) {
    float* S  = sm_attn;             // [64][516]
    float* Qt = sm_attn + QT_OFF;    // [64][68]   ([d][q])
    float* KV = sm_attn + KV_OFF;    // Kt [64][260] ([d][kcol]) / Vs [64][68]

    const int bh = blockIdx.x;
    const int b  = bh >> 4;
    const int h  = bh & 15;
    const int q0 = blockIdx.y * 64;
    const int lt = threadIdx.x;

    const float* qTb = qT + (size_t)bh*DHH*TT;
    const float* kTb = kT + (size_t)bh*DHH*TT;
    const float* vb  = v  + (size_t)bh*TT*DHH;
    const float* mb  = maskp + (size_t)b*HWW*HWW;

    // load Q tile transposed: Qt[d][qlocal]
    #pragma unroll
    for (int it = 0; it < 4; it++) {
        int idx4 = lt + 256*it;
        int kd = idx4 >> 4, q4 = (idx4 & 15) * 4;
        *(float4*)&Qt[kd*68 + q4] = *(const float4*)&qTb[(size_t)kd*TT + q0 + q4];
    }

    const int qg = lt >> 5;          // 0..7  (8 q-rows each)
    const int cg = lt & 31;          // 0..31 (8 k-cols each)
    const bool maskq = (q0 < HWW);

    for (int kt = 0; kt < 2; kt++) {
        __syncthreads();
        // load K chunk transposed: Kt[d][c], c in [0,256)
        #pragma unroll
        for (int it = 0; it < 16; it++) {
            int idx4 = lt + 256*it;
            int kd = idx4 >> 6, c4 = (idx4 & 63) * 4;
            *(float4*)&KV[kd*260 + c4] =
                *(const float4*)&kTb[(size_t)kd*TT + kt*256 + c4];
        }
        __syncthreads();

        float acc[8][8];
        #pragma unroll
        for (int i = 0; i < 8; i++)
            #pragma unroll
            for (int j = 0; j < 8; j++) acc[i][j] = 0.f;

        #pragma unroll 8
        for (int kd = 0; kd < 64; kd++) {
            float4 a0 = *(const float4*)&Qt[kd*68 + qg*8];
            float4 a1 = *(const float4*)&Qt[kd*68 + qg*8 + 4];
            float4 b0 = *(const float4*)&KV[kd*260 + cg*8];
            float4 b1 = *(const float4*)&KV[kd*260 + cg*8 + 4];
            float ra[8] = {a0.x,a0.y,a0.z,a0.w,a1.x,a1.y,a1.z,a1.w};
            float rb[8] = {b0.x,b0.y,b0.z,b0.w,b1.x,b1.y,b1.z,b1.w};
            #pragma unroll
            for (int i = 0; i < 8; i++)
                #pragma unroll
                for (int j = 0; j < 8; j++)
                    acc[i][j] += ra[i] * rb[j];
        }

        // scale (+mask) and store S chunk
        const bool masked = maskq && (kt == 0);
        #pragma unroll
        for (int i = 0; i < 8; i++) {
            int q = qg*8 + i;
            float w[8];
            if (masked) {
                float4 m0 = *(const float4*)&mb[(size_t)(q0+q)*HWW + cg*8];
                float4 m1 = *(const float4*)&mb[(size_t)(q0+q)*HWW + cg*8 + 4];
                w[0]=0.125f*m0.x; w[1]=0.125f*m0.y; w[2]=0.125f*m0.z; w[3]=0.125f*m0.w;
                w[4]=0.125f*m1.x; w[5]=0.125f*m1.y; w[6]=0.125f*m1.z; w[7]=0.125f*m1.w;
            } else {
                #pragma unroll
                for (int j = 0; j < 8; j++) w[j] = 0.125f;
            }
            float* Sp = &S[q*S_PAD + kt*256 + cg*8];
            *(float4*)Sp       = make_float4(acc[i][0]*w[0], acc[i][1]*w[1],
                                             acc[i][2]*w[2], acc[i][3]*w[3]);
            *(float4*)(Sp + 4) = make_float4(acc[i][4]*w[4], acc[i][5]*w[5],
                                             acc[i][6]*w[6], acc[i][7]*w[7]);
        }
    }
    __syncthreads();

    // ---- softmax: warp w owns rows w*8 .. w*8+7 ----
    {
        const int w = lt >> 5, lane = lt & 31;
        for (int rr = 0; rr < 8; rr++) {
            float* Sr = &S[(w*8 + rr)*S_PAD];
            float vals[16];
            float mx = -1e30f;
            #pragma unroll
            for (int i = 0; i < 16; i++) {
                vals[i] = Sr[i*32 + lane];
                mx = fmaxf(mx, vals[i]);
            }
            #pragma unroll
            for (int o = 16; o > 0; o >>= 1)
                mx = fmaxf(mx, __shfl_xor_sync(0xffffffffu, mx, o));
            float sum = 0.f;
            #pragma unroll
            for (int i = 0; i < 16; i++) {
                vals[i] = __expf(vals[i] - mx);
                sum += vals[i];
            }
            #pragma unroll
            for (int o = 16; o > 0; o >>= 1)
                sum += __shfl_xor_sync(0xffffffffu, sum, o);
            float inv = 1.f / sum;
            #pragma unroll
            for (int i = 0; i < 16; i++)
                Sr[i*32 + lane] = vals[i] * inv;
        }
    }

    // ---- O = P @ V : 4x4 microtile ----
    const int rg = lt >> 4;          // 0..15 -> 4 q-rows
    const int cd = (lt & 15) * 4;    // 4 d-cols
    float o[4][4];
    #pragma unroll
    for (int r = 0; r < 4; r++)
        #pragma unroll
        for (int c = 0; c < 4; c++) o[r][c] = 0.f;

    for (int vt = 0; vt < 8; vt++) {
        __syncthreads();
        #pragma unroll
        for (int it = 0; it < 4; it++) {
            int idx4 = lt + 256*it;
            int kr = idx4 >> 4, d4 = (idx4 & 15) * 4;
            *(float4*)&KV[kr*68 + d4] =
                *(const float4*)&vb[(size_t)(vt*64 + kr)*DHH + d4];
        }
        __syncthreads();

        #pragma unroll 4
        for (int k0 = 0; k0 < 64; k0 += 4) {
            float4 p[4], vv[4];
            #pragma unroll
            for (int r = 0; r < 4; r++)
                p[r] = *(const float4*)&S[(rg*4 + r)*S_PAD + vt*64 + k0];
            #pragma unroll
            for (int kk = 0; kk < 4; kk++)
                vv[kk] = *(const float4*)&KV[(k0 + kk)*68 + cd];
            #pragma unroll
            for (int r = 0; r < 4; r++) {
                float pr[4] = {p[r].x, p[r].y, p[r].z, p[r].w};
                o[r][0] += pr[0]*vv[0].x + pr[1]*vv[1].x + pr[2]*vv[2].x + pr[3]*vv[3].x;
                o[r][1] += pr[0]*vv[0].y + pr[1]*vv[1].y + pr[2]*vv[2].y + pr[3]*vv[3].y;
                o[r][2] += pr[0]*vv[0].z + pr[1]*vv[1].z + pr[2]*vv[2].z + pr[3]*vv[3].z;
                o[r][3] += pr[0]*vv[0].w + pr[1]*vv[1].w + pr[2]*vv[2].w + pr[3]*vv[3].w;
            }
        }
    }

    #pragma unroll
    for (int r = 0; r < 4; r++) {
        int q = q0 + rg*4 + r;
        *(float4*)&y[(size_t)(b*TT + q)*CC + h*DHH + cd] =
            make_float4(o[r][0], o[r][1], o[r][2], o[r][3]);
    }
}

// ---------------------------------------------------------------------------
extern "C" void kernel_launch(void* const* d_in, const int* in_sizes, int n_in,
                              void* d_out, int out_size) {
    const float* x    = (const float*)d_in[0];
    const float* src  = (const float*)d_in[1];
    const float* fwd  = (const float*)d_in[2];
    const float* bwd  = (const float*)d_in[3];
    const float* Wq   = (const float*)d_in[4];
    const float* bq   = (const float*)d_in[5];
    const float* Wk   = (const float*)d_in[6];
    const float* bk   = (const float*)d_in[7];
    const float* Wv   = (const float*)d_in[8];
    const float* bv   = (const float*)d_in[9];
    const float* Wp   = (const float*)d_in[10];
    const float* bp   = (const float*)d_in[11];
    float* out = (float*)d_out;

    float *pq, *pk, *pv, *pqT, *pkT, *pm, *py;
    cudaGetSymbolAddress((void**)&pq,  g_q);
    cudaGetSymbolAddress((void**)&pk,  g_k);
    cudaGetSymbolAddress((void**)&pv,  g_v);
    cudaGetSymbolAddress((void**)&pqT, g_qT);
    cudaGetSymbolAddress((void**)&pkT, g_kT);
    cudaGetSymbolAddress((void**)&pm,  g_mask);
    cudaGetSymbolAddress((void**)&py,  g_y);

    cudaFuncSetAttribute(attn2, cudaFuncAttributeMaxDynamicSharedMemorySize, ATTN_SMEM);

    dim3 ggrid(CC/128, MM/128);
    gemm128<<<ggrid, 256>>>(x,   Wq, bq, pq, 1);
    gemm128<<<ggrid, 256>>>(src, Wk, bk, pk, 1);
    gemm128<<<ggrid, 256>>>(src, Wv, bv, pv, 1);

    dim3 tgrid(2, 16, BB*NHH);
    dim3 tblk(32, 8);
    trans_td<<<tgrid, tblk>>>(pq, pqT);
    trans_td<<<tgrid, tblk>>>(pk, pkT);

    dim3 mgrid(8, 8, BB);
    mask_prod<<<mgrid, tblk>>>(fwd, bwd, pm);

    dim3 agrid(BB*NHH, TT/64);       // (128, 8)
    attn2<<<agrid, 256, ATTN_SMEM>>>(pqT, pkT, pv, pm, py);

    gemm128<<<ggrid, 256>>>(py, Wp, bp, out, 0);
}

// round 6
// speedup vs baseline: 2.6000x; 1.8440x over previous
#include <cuda_runtime.h>
#include <cuda_bf16.h>
#include <cstdint>

#define BB   8
#define TT   512
#define CC   1024
#define NHH  16
#define DHH  64
#define HWW  256
#define MM   (BB*TT)

// Scratch
__device__ float g_q [BB*NHH*TT*DHH];   // [bh][t][d]
__device__ float g_k [BB*NHH*TT*DHH];
__device__ float g_v [BB*NHH*TT*DHH];
__device__ float g_qT[BB*NHH*DHH*TT];   // [bh][d][t]
__device__ float g_kT[BB*NHH*DHH*TT];
__device__ float g_mask[BB*HWW*HWW];
__device__ float g_y [MM*CC];

extern __shared__ __align__(1024) unsigned char dynsm[];

// ---------------------------------------------------------------------------
// mma.sync bf16 GEMM (Ampere-style path — compiles for plain sm_100 target)
// out[m,n] = sum_k A[m,k]*W[n,k] + bias[n]
// Split bf16: D += Ahi*Bhi + Ahi*Blo + Alo*Bhi  (fp32-grade accuracy)
// CTA tile 128x128, K chunks of 32 fp32, 8 warps (2x4), warp tile 64x32.
// SMEM: hi/lo bf16 operands, row stride 40 halves, double-buffered = 81920 B
// ---------------------------------------------------------------------------
#define ASTR   40            // halves per row (20-bank stride, conflict-free)
#define BUFH   20480         // halves per stage (4 arrays * 128*40)
#define AHI_O  0
#define ALO_O  5120
#define BHI_O  10240
#define BLO_O  15360
#define GEMM_SMEM (2*BUFH*2) // bytes

#define MMA16816(d, a, b) \
    asm volatile("mma.sync.aligned.m16n8k16.row.col.f32.bf16.bf16.f32 " \
        "{%0,%1,%2,%3}, {%4,%5,%6,%7}, {%8,%9}, {%0,%1,%2,%3};" \
        : "+f"((d)[0]), "+f"((d)[1]), "+f"((d)[2]), "+f"((d)[3]) \
        : "r"((a)[0]), "r"((a)[1]), "r"((a)[2]), "r"((a)[3]), \
          "r"((b)[0]), "r"((b)[1]))

__device__ __forceinline__ void split_store(__nv_bfloat16* hi, __nv_bfloat16* lo,
                                            float4 a) {
    __nv_bfloat16 h0 = __float2bfloat16_rn(a.x);
    __nv_bfloat16 h1 = __float2bfloat16_rn(a.y);
    __nv_bfloat16 h2 = __float2bfloat16_rn(a.z);
    __nv_bfloat16 h3 = __float2bfloat16_rn(a.w);
    __nv_bfloat16 l0 = __float2bfloat16_rn(a.x - __bfloat162float(h0));
    __nv_bfloat16 l1 = __float2bfloat16_rn(a.y - __bfloat162float(h1));
    __nv_bfloat16 l2 = __float2bfloat16_rn(a.z - __bfloat162float(h2));
    __nv_bfloat16 l3 = __float2bfloat16_rn(a.w - __bfloat162float(h3));
    union { __nv_bfloat162 b; uint32_t u; } p0, p1, q0, q1;
    p0.b = __halves2bfloat162(h0, h1); p1.b = __halves2bfloat162(h2, h3);
    q0.b = __halves2bfloat162(l0, l1); q1.b = __halves2bfloat162(l2, l3);
    *(uint2*)hi = make_uint2(p0.u, p1.u);
    *(uint2*)lo = make_uint2(q0.u, q1.u);
}

__global__ __launch_bounds__(256, 1) void gemm_mma(const float* __restrict__ A,
                                                   const float* __restrict__ W,
                                                   const float* __restrict__ bias,
                                                   float* __restrict__ out,
                                                   int heads) {
    __nv_bfloat16* sm = (__nv_bfloat16*)dynsm;

    const int lt   = threadIdx.x;
    const int w    = lt >> 5;
    const int lane = lt & 31;
    const int wm   = w & 1;          // 0..1  (64 m-rows)
    const int wn   = w >> 1;         // 0..3  (32 n-cols)
    const int gid  = lane >> 2;      // 0..7
    const int tid  = lane & 3;       // 0..3
    const int row0 = blockIdx.y * 128;
    const int col0 = blockIdx.x * 128;

    const float* Ab = A + (size_t)row0 * CC;
    const float* Wb = W + (size_t)col0 * CC;

    float acc[4][4][4];
    #pragma unroll
    for (int mt = 0; mt < 4; mt++)
        #pragma unroll
        for (int nt = 0; nt < 4; nt++)
            #pragma unroll
            for (int e = 0; e < 4; e++) acc[mt][nt][e] = 0.f;

    // staging regs: 4 float4 for A, 4 for B  (idx = lt + 256*i)
    float4 stA[4], stB[4];

    #define LOADCH(c)                                                        \
        do {                                                                 \
            _Pragma("unroll")                                                \
            for (int i = 0; i < 4; i++) {                                    \
                int idx = lt + 256*i;                                        \
                int r   = idx >> 3;                                          \
                int kq  = (idx & 7) * 4;                                     \
                stA[i] = *(const float4*)&Ab[(size_t)r*CC + (c)*32 + kq];    \
                stB[i] = *(const float4*)&Wb[(size_t)r*CC + (c)*32 + kq];    \
            }                                                                \
        } while (0)

    #define STORECH(s)                                                       \
        do {                                                                 \
            __nv_bfloat16* bp = sm + (s)*BUFH;                               \
            _Pragma("unroll")                                                \
            for (int i = 0; i < 4; i++) {                                    \
                int idx = lt + 256*i;                                        \
                int r   = idx >> 3;                                          \
                int kq  = (idx & 7) * 4;                                     \
                split_store(bp + AHI_O + r*ASTR + kq,                        \
                            bp + ALO_O + r*ASTR + kq, stA[i]);               \
                split_store(bp + BHI_O + r*ASTR + kq,                        \
                            bp + BLO_O + r*ASTR + kq, stB[i]);               \
            }                                                                \
        } while (0)

    LOADCH(0);
    STORECH(0);
    __syncthreads();

    for (int c = 0; c < 32; c++) {
        if (c < 31) LOADCH(c + 1);

        const __nv_bfloat16* bp  = sm + (c & 1)*BUFH;
        const __nv_bfloat16* Ahi = bp + AHI_O;
        const __nv_bfloat16* Alo = bp + ALO_O;
        const __nv_bfloat16* Bhi = bp + BHI_O;
        const __nv_bfloat16* Blo = bp + BLO_O;

        #pragma unroll
        for (int k16 = 0; k16 < 32; k16 += 16) {
            uint32_t ah[4][4], al[4][4], bh[4][2], bl[4][2];
            #pragma unroll
            for (int mt = 0; mt < 4; mt++) {
                int r = wm*64 + mt*16 + gid;
                ah[mt][0] = *(const uint32_t*)(Ahi + r*ASTR     + k16 + tid*2);
                ah[mt][1] = *(const uint32_t*)(Ahi + (r+8)*ASTR + k16 + tid*2);
                ah[mt][2] = *(const uint32_t*)(Ahi + r*ASTR     + k16 + 8 + tid*2);
                ah[mt][3] = *(const uint32_t*)(Ahi + (r+8)*ASTR + k16 + 8 + tid*2);
                al[mt][0] = *(const uint32_t*)(Alo + r*ASTR     + k16 + tid*2);
                al[mt][1] = *(const uint32_t*)(Alo + (r+8)*ASTR + k16 + tid*2);
                al[mt][2] = *(const uint32_t*)(Alo + r*ASTR     + k16 + 8 + tid*2);
                al[mt][3] = *(const uint32_t*)(Alo + (r+8)*ASTR + k16 + 8 + tid*2);
            }
            #pragma unroll
            for (int nt = 0; nt < 4; nt++) {
                int n = wn*32 + nt*8 + gid;
                bh[nt][0] = *(const uint32_t*)(Bhi + n*ASTR + k16 + tid*2);
                bh[nt][1] = *(const uint32_t*)(Bhi + n*ASTR + k16 + 8 + tid*2);
                bl[nt][0] = *(const uint32_t*)(Blo + n*ASTR + k16 + tid*2);
                bl[nt][1] = *(const uint32_t*)(Blo + n*ASTR + k16 + 8 + tid*2);
            }
            #pragma unroll
            for (int mt = 0; mt < 4; mt++)
                #pragma unroll
                for (int nt = 0; nt < 4; nt++) {
                    MMA16816(acc[mt][nt], ah[mt], bh[nt]);
                    MMA16816(acc[mt][nt], ah[mt], bl[nt]);
                    MMA16816(acc[mt][nt], al[mt], bh[nt]);
                }
        }

        if (c < 31) STORECH((c + 1) & 1);
        __syncthreads();
    }

    // epilogue
    #pragma unroll
    for (int mt = 0; mt < 4; mt++) {
        #pragma unroll
        for (int nt = 0; nt < 4; nt++) {
            int n  = col0 + wn*32 + nt*8 + tid*2;
            float b0 = bias[n], b1 = bias[n+1];
            #pragma unroll
            for (int half = 0; half < 2; half++) {
                int m  = row0 + wm*64 + mt*16 + gid + half*8;
                float v0 = acc[mt][nt][half*2+0] + b0;
                float v1 = acc[mt][nt][half*2+1] + b1;
                float* op;
                if (heads) {
                    int bb = m >> 9, t = m & 511;
                    op = out + ((size_t)((bb*NHH + (n >> 6))*TT + t))*DHH + (n & 63);
                } else {
                    op = out + (size_t)m*CC + n;
                }
                op[0] = v0; op[1] = v1;
            }
        }
    }
    #undef LOADCH
    #undef STORECH
}

// ---------------------------------------------------------------------------
// Transpose [bh][t=512][d=64] -> [bh][d=64][t=512]
// ---------------------------------------------------------------------------
__global__ void trans_td(const float* __restrict__ in, float* __restrict__ out) {
    __shared__ float tile[32][33];
    const int bh = blockIdx.z;
    const int d0 = blockIdx.x * 32, t0 = blockIdx.y * 32;
    const float* ip = in  + (size_t)bh*TT*DHH;
    float*       op = out + (size_t)bh*DHH*TT;
    const int tx = threadIdx.x, ty = threadIdx.y;
    #pragma unroll
    for (int i = 0; i < 32; i += 8)
        tile[ty+i][tx] = ip[(size_t)(t0+ty+i)*DHH + d0 + tx];
    __syncthreads();
    #pragma unroll
    for (int i = 0; i < 32; i += 8)
        op[(size_t)(d0+ty+i)*TT + t0 + tx] = tile[tx][ty+i];
}

// ---------------------------------------------------------------------------
// mask[b][q][k] = fwd[b][q][k] * bwd[b][k][q]
// ---------------------------------------------------------------------------
__global__ void mask_prod(const float* __restrict__ fwd,
                          const float* __restrict__ bwd,
                          float* __restrict__ out) {
    __shared__ float tile[32][33];
    const int b  = blockIdx.z;
    const int x0 = blockIdx.x * 32, y0 = blockIdx.y * 32;
    const float* fp = fwd + (size_t)b*HWW*HWW;
    const float* bp = bwd + (size_t)b*HWW*HWW;
    float*       op = out + (size_t)b*HWW*HWW;
    const int tx = threadIdx.x, ty = threadIdx.y;
    #pragma unroll
    for (int i = 0; i < 32; i += 8)
        tile[ty+i][tx] = bp[(size_t)(y0+ty+i)*HWW + x0 + tx];
    __syncthreads();
    #pragma unroll
    for (int i = 0; i < 32; i += 8) {
        int q = x0 + ty + i;
        int k = y0 + tx;
        op[(size_t)q*HWW + k] = fp[(size_t)q*HWW + k] * tile[tx][ty+i];
    }
}

// ---------------------------------------------------------------------------
// Attention (register-blocked fp32, from R3 — passing, shared-pipe balanced)
// ---------------------------------------------------------------------------
#define S_PAD  516
#define QT_OFF 33024
#define KV_OFF 37376
#define ATTN_SMEM (54016*4)

__global__ __launch_bounds__(256, 1) void attn2(const float* __restrict__ qT,
                                                const float* __restrict__ kT,
                                                const float* __restrict__ v,
                                                const float* __restrict__ maskp,
                                                float* __restrict__ y) {
    float* sm_attn = (float*)dynsm;
    float* S  = sm_attn;
    float* Qt = sm_attn + QT_OFF;
    float* KV = sm_attn + KV_OFF;

    const int bh = blockIdx.x;
    const int b  = bh >> 4;
    const int h  = bh & 15;
    const int q0 = blockIdx.y * 64;
    const int lt = threadIdx.x;

    const float* qTb = qT + (size_t)bh*DHH*TT;
    const float* kTb = kT + (size_t)bh*DHH*TT;
    const float* vb  = v  + (size_t)bh*TT*DHH;
    const float* mb  = maskp + (size_t)b*HWW*HWW;

    #pragma unroll
    for (int it = 0; it < 4; it++) {
        int idx4 = lt + 256*it;
        int kd = idx4 >> 4, q4 = (idx4 & 15) * 4;
        *(float4*)&Qt[kd*68 + q4] = *(const float4*)&qTb[(size_t)kd*TT + q0 + q4];
    }

    const int qg = lt >> 5;
    const int cg = lt & 31;
    const bool maskq = (q0 < HWW);

    for (int kt = 0; kt < 2; kt++) {
        __syncthreads();
        #pragma unroll
        for (int it = 0; it < 16; it++) {
            int idx4 = lt + 256*it;
            int kd = idx4 >> 6, c4 = (idx4 & 63) * 4;
            *(float4*)&KV[kd*260 + c4] =
                *(const float4*)&kTb[(size_t)kd*TT + kt*256 + c4];
        }
        __syncthreads();

        float acc[8][8];
        #pragma unroll
        for (int i = 0; i < 8; i++)
            #pragma unroll
            for (int j = 0; j < 8; j++) acc[i][j] = 0.f;

        #pragma unroll 8
        for (int kd = 0; kd < 64; kd++) {
            float4 a0 = *(const float4*)&Qt[kd*68 + qg*8];
            float4 a1 = *(const float4*)&Qt[kd*68 + qg*8 + 4];
            float4 b0 = *(const float4*)&KV[kd*260 + cg*8];
            float4 b1 = *(const float4*)&KV[kd*260 + cg*8 + 4];
            float ra[8] = {a0.x,a0.y,a0.z,a0.w,a1.x,a1.y,a1.z,a1.w};
            float rb[8] = {b0.x,b0.y,b0.z,b0.w,b1.x,b1.y,b1.z,b1.w};
            #pragma unroll
            for (int i = 0; i < 8; i++)
                #pragma unroll
                for (int j = 0; j < 8; j++)
                    acc[i][j] += ra[i] * rb[j];
        }

        const bool masked = maskq && (kt == 0);
        #pragma unroll
        for (int i = 0; i < 8; i++) {
            int q = qg*8 + i;
            float w[8];
            if (masked) {
                float4 m0 = *(const float4*)&mb[(size_t)(q0+q)*HWW + cg*8];
                float4 m1 = *(const float4*)&mb[(size_t)(q0+q)*HWW + cg*8 + 4];
                w[0]=0.125f*m0.x; w[1]=0.125f*m0.y; w[2]=0.125f*m0.z; w[3]=0.125f*m0.w;
                w[4]=0.125f*m1.x; w[5]=0.125f*m1.y; w[6]=0.125f*m1.z; w[7]=0.125f*m1.w;
            } else {
                #pragma unroll
                for (int j = 0; j < 8; j++) w[j] = 0.125f;
            }
            float* Sp = &S[q*S_PAD + kt*256 + cg*8];
            *(float4*)Sp       = make_float4(acc[i][0]*w[0], acc[i][1]*w[1],
                                             acc[i][2]*w[2], acc[i][3]*w[3]);
            *(float4*)(Sp + 4) = make_float4(acc[i][4]*w[4], acc[i][5]*w[5],
                                             acc[i][6]*w[6], acc[i][7]*w[7]);
        }
    }
    __syncthreads();

    {
        const int w = lt >> 5, lane = lt & 31;
        for (int rr = 0; rr < 8; rr++) {
            float* Sr = &S[(w*8 + rr)*S_PAD];
            float vals[16];
            float mx = -1e30f;
            #pragma unroll
            for (int i = 0; i < 16; i++) {
                vals[i] = Sr[i*32 + lane];
                mx = fmaxf(mx, vals[i]);
            }
            #pragma unroll
            for (int o = 16; o > 0; o >>= 1)
                mx = fmaxf(mx, __shfl_xor_sync(0xffffffffu, mx, o));
            float sum = 0.f;
            #pragma unroll
            for (int i = 0; i < 16; i++) {
                vals[i] = __expf(vals[i] - mx);
                sum += vals[i];
            }
            #pragma unroll
            for (int o = 16; o > 0; o >>= 1)
                sum += __shfl_xor_sync(0xffffffffu, sum, o);
            float inv = 1.f / sum;
            #pragma unroll
            for (int i = 0; i < 16; i++)
                Sr[i*32 + lane] = vals[i] * inv;
        }
    }

    const int rg = lt >> 4;
    const int cd = (lt & 15) * 4;
    float o[4][4];
    #pragma unroll
    for (int r = 0; r < 4; r++)
        #pragma unroll
        for (int c = 0; c < 4; c++) o[r][c] = 0.f;

    for (int vt = 0; vt < 8; vt++) {
        __syncthreads();
        #pragma unroll
        for (int it = 0; it < 4; it++) {
            int idx4 = lt + 256*it;
            int kr = idx4 >> 4, d4 = (idx4 & 15) * 4;
            *(float4*)&KV[kr*68 + d4] =
                *(const float4*)&vb[(size_t)(vt*64 + kr)*DHH + d4];
        }
        __syncthreads();

        #pragma unroll 4
        for (int k0 = 0; k0 < 64; k0 += 4) {
            float4 p[4], vv[4];
            #pragma unroll
            for (int r = 0; r < 4; r++)
                p[r] = *(const float4*)&S[(rg*4 + r)*S_PAD + vt*64 + k0];
            #pragma unroll
            for (int kk = 0; kk < 4; kk++)
                vv[kk] = *(const float4*)&KV[(k0 + kk)*68 + cd];
            #pragma unroll
            for (int r = 0; r < 4; r++) {
                float pr[4] = {p[r].x, p[r].y, p[r].z, p[r].w};
                o[r][0] += pr[0]*vv[0].x + pr[1]*vv[1].x + pr[2]*vv[2].x + pr[3]*vv[3].x;
                o[r][1] += pr[0]*vv[0].y + pr[1]*vv[1].y + pr[2]*vv[2].y + pr[3]*vv[3].y;
                o[r][2] += pr[0]*vv[0].z + pr[1]*vv[1].z + pr[2]*vv[2].z + pr[3]*vv[3].z;
                o[r][3] += pr[0]*vv[0].w + pr[1]*vv[1].w + pr[2]*vv[2].w + pr[3]*vv[3].w;
            }
        }
    }

    #pragma unroll
    for (int r = 0; r < 4; r++) {
        int q = q0 + rg*4 + r;
        *(float4*)&y[(size_t)(b*TT + q)*CC + h*DHH + cd] =
            make_float4(o[r][0], o[r][1], o[r][2], o[r][3]);
    }
}

// ---------------------------------------------------------------------------
extern "C" void kernel_launch(void* const* d_in, const int* in_sizes, int n_in,
                              void* d_out, int out_size) {
    const float* x    = (const float*)d_in[0];
    const float* src  = (const float*)d_in[1];
    const float* fwd  = (const float*)d_in[2];
    const float* bwd  = (const float*)d_in[3];
    const float* Wq   = (const float*)d_in[4];
    const float* bq   = (const float*)d_in[5];
    const float* Wk   = (const float*)d_in[6];
    const float* bk   = (const float*)d_in[7];
    const float* Wv   = (const float*)d_in[8];
    const float* bv   = (const float*)d_in[9];
    const float* Wp   = (const float*)d_in[10];
    const float* bp   = (const float*)d_in[11];
    float* out = (float*)d_out;

    float *pq, *pk, *pv, *pqT, *pkT, *pm, *py;
    cudaGetSymbolAddress((void**)&pq,  g_q);
    cudaGetSymbolAddress((void**)&pk,  g_k);
    cudaGetSymbolAddress((void**)&pv,  g_v);
    cudaGetSymbolAddress((void**)&pqT, g_qT);
    cudaGetSymbolAddress((void**)&pkT, g_kT);
    cudaGetSymbolAddress((void**)&pm,  g_mask);
    cudaGetSymbolAddress((void**)&py,  g_y);

    cudaFuncSetAttribute(gemm_mma, cudaFuncAttributeMaxDynamicSharedMemorySize, GEMM_SMEM);
    cudaFuncSetAttribute(attn2,    cudaFuncAttributeMaxDynamicSharedMemorySize, ATTN_SMEM);

    dim3 ggrid(CC/128, MM/128);      // (8, 32)
    gemm_mma<<<ggrid, 256, GEMM_SMEM>>>(x,   Wq, bq, pq, 1);
    gemm_mma<<<ggrid, 256, GEMM_SMEM>>>(src, Wk, bk, pk, 1);
    gemm_mma<<<ggrid, 256, GEMM_SMEM>>>(src, Wv, bv, pv, 1);

    dim3 tgrid(2, 16, BB*NHH);
    dim3 tblk(32, 8);
    trans_td<<<tgrid, tblk>>>(pq, pqT);
    trans_td<<<tgrid, tblk>>>(pk, pkT);

    dim3 mgrid(8, 8, BB);
    mask_prod<<<mgrid, tblk>>>(fwd, bwd, pm);

    dim3 agrid(BB*NHH, TT/64);       // (128, 8)
    attn2<<<agrid, 256, ATTN_SMEM>>>(pqT, pkT, pv, pm, py);

    gemm_mma<<<ggrid, 256, GEMM_SMEM>>>(py, Wp, bp, out, 0);
}

// round 7
// speedup vs baseline: 3.1106x; 1.1964x over previous
#include <cuda_runtime.h>
#include <cuda_bf16.h>
#include <cstdint>

#define BB   8
#define TT   512
#define CC   1024
#define NHH  16
#define DHH  64
#define HWW  256
#define MM   (BB*TT)

// Scratch
__device__ float g_q [BB*NHH*TT*DHH];   // [bh][t][d]
__device__ float g_k [BB*NHH*TT*DHH];
__device__ float g_v [BB*NHH*TT*DHH];
__device__ float g_vT[BB*NHH*DHH*TT];   // [bh][d][t]
__device__ float g_mask[BB*HWW*HWW];    // [b][q][k] = fwd[q][k]*bwd[k][q]
__device__ float g_y [MM*CC];

extern __shared__ __align__(1024) unsigned char dynsm[];

// ---------------------------------------------------------------------------
// Common helpers
// ---------------------------------------------------------------------------
#define MMA16816(d, a, b) \
    asm volatile("mma.sync.aligned.m16n8k16.row.col.f32.bf16.bf16.f32 " \
        "{%0,%1,%2,%3}, {%4,%5,%6,%7}, {%8,%9}, {%0,%1,%2,%3};" \
        : "+f"((d)[0]), "+f"((d)[1]), "+f"((d)[2]), "+f"((d)[3]) \
        : "r"((a)[0]), "r"((a)[1]), "r"((a)[2]), "r"((a)[3]), \
          "r"((b)[0]), "r"((b)[1]))

__device__ __forceinline__ void split_store(__nv_bfloat16* hi, __nv_bfloat16* lo,
                                            float4 a) {
    __nv_bfloat16 h0 = __float2bfloat16_rn(a.x);
    __nv_bfloat16 h1 = __float2bfloat16_rn(a.y);
    __nv_bfloat16 h2 = __float2bfloat16_rn(a.z);
    __nv_bfloat16 h3 = __float2bfloat16_rn(a.w);
    __nv_bfloat16 l0 = __float2bfloat16_rn(a.x - __bfloat162float(h0));
    __nv_bfloat16 l1 = __float2bfloat16_rn(a.y - __bfloat162float(h1));
    __nv_bfloat16 l2 = __float2bfloat16_rn(a.z - __bfloat162float(h2));
    __nv_bfloat16 l3 = __float2bfloat16_rn(a.w - __bfloat162float(h3));
    union { __nv_bfloat162 b; uint32_t u; } p0, p1, q0, q1;
    p0.b = __halves2bfloat162(h0, h1); p1.b = __halves2bfloat162(h2, h3);
    q0.b = __halves2bfloat162(l0, l1); q1.b = __halves2bfloat162(l2, l3);
    *(uint2*)hi = make_uint2(p0.u, p1.u);
    *(uint2*)lo = make_uint2(q0.u, q1.u);
}

// ---------------------------------------------------------------------------
// Projection GEMM via mma.sync split-bf16 (from R6, passing)
// ---------------------------------------------------------------------------
#define ASTR   40
#define BUFH   20480
#define AHI_O  0
#define ALO_O  5120
#define BHI_O  10240
#define BLO_O  15360
#define GEMM_SMEM (2*BUFH*2)

__global__ __launch_bounds__(256, 1) void gemm_mma(const float* __restrict__ A,
                                                   const float* __restrict__ W,
                                                   const float* __restrict__ bias,
                                                   float* __restrict__ out,
                                                   int heads) {
    __nv_bfloat16* sm = (__nv_bfloat16*)dynsm;

    const int lt   = threadIdx.x;
    const int w    = lt >> 5;
    const int lane = lt & 31;
    const int wm   = w & 1;
    const int wn   = w >> 1;
    const int gid  = lane >> 2;
    const int tid  = lane & 3;
    const int row0 = blockIdx.y * 128;
    const int col0 = blockIdx.x * 128;

    const float* Ab = A + (size_t)row0 * CC;
    const float* Wb = W + (size_t)col0 * CC;

    float acc[4][4][4];
    #pragma unroll
    for (int mt = 0; mt < 4; mt++)
        #pragma unroll
        for (int nt = 0; nt < 4; nt++)
            #pragma unroll
            for (int e = 0; e < 4; e++) acc[mt][nt][e] = 0.f;

    float4 stA[4], stB[4];

    #define LOADCH(c)                                                        \
        do {                                                                 \
            _Pragma("unroll")                                                \
            for (int i = 0; i < 4; i++) {                                    \
                int idx = lt + 256*i;                                        \
                int r   = idx >> 3;                                          \
                int kq  = (idx & 7) * 4;                                     \
                stA[i] = *(const float4*)&Ab[(size_t)r*CC + (c)*32 + kq];    \
                stB[i] = *(const float4*)&Wb[(size_t)r*CC + (c)*32 + kq];    \
            }                                                                \
        } while (0)

    #define STORECH(s)                                                       \
        do {                                                                 \
            __nv_bfloat16* bp = sm + (s)*BUFH;                               \
            _Pragma("unroll")                                                \
            for (int i = 0; i < 4; i++) {                                    \
                int idx = lt + 256*i;                                        \
                int r   = idx >> 3;                                          \
                int kq  = (idx & 7) * 4;                                     \
                split_store(bp + AHI_O + r*ASTR + kq,                        \
                            bp + ALO_O + r*ASTR + kq, stA[i]);               \
                split_store(bp + BHI_O + r*ASTR + kq,                        \
                            bp + BLO_O + r*ASTR + kq, stB[i]);               \
            }                                                                \
        } while (0)

    LOADCH(0);
    STORECH(0);
    __syncthreads();

    for (int c = 0; c < 32; c++) {
        if (c < 31) LOADCH(c + 1);

        const __nv_bfloat16* bp  = sm + (c & 1)*BUFH;
        const __nv_bfloat16* Ahi = bp + AHI_O;
        const __nv_bfloat16* Alo = bp + ALO_O;
        const __nv_bfloat16* Bhi = bp + BHI_O;
        const __nv_bfloat16* Blo = bp + BLO_O;

        #pragma unroll
        for (int k16 = 0; k16 < 32; k16 += 16) {
            uint32_t ah[4][4], al[4][4], fb_h[4][2], fb_l[4][2];
            #pragma unroll
            for (int mt = 0; mt < 4; mt++) {
                int r = wm*64 + mt*16 + gid;
                ah[mt][0] = *(const uint32_t*)(Ahi + r*ASTR     + k16 + tid*2);
                ah[mt][1] = *(const uint32_t*)(Ahi + (r+8)*ASTR + k16 + tid*2);
                ah[mt][2] = *(const uint32_t*)(Ahi + r*ASTR     + k16 + 8 + tid*2);
                ah[mt][3] = *(const uint32_t*)(Ahi + (r+8)*ASTR + k16 + 8 + tid*2);
                al[mt][0] = *(const uint32_t*)(Alo + r*ASTR     + k16 + tid*2);
                al[mt][1] = *(const uint32_t*)(Alo + (r+8)*ASTR + k16 + tid*2);
                al[mt][2] = *(const uint32_t*)(Alo + r*ASTR     + k16 + 8 + tid*2);
                al[mt][3] = *(const uint32_t*)(Alo + (r+8)*ASTR + k16 + 8 + tid*2);
            }
            #pragma unroll
            for (int nt = 0; nt < 4; nt++) {
                int n = wn*32 + nt*8 + gid;
                fb_h[nt][0] = *(const uint32_t*)(Bhi + n*ASTR + k16 + tid*2);
                fb_h[nt][1] = *(const uint32_t*)(Bhi + n*ASTR + k16 + 8 + tid*2);
                fb_l[nt][0] = *(const uint32_t*)(Blo + n*ASTR + k16 + tid*2);
                fb_l[nt][1] = *(const uint32_t*)(Blo + n*ASTR + k16 + 8 + tid*2);
            }
            #pragma unroll
            for (int mt = 0; mt < 4; mt++)
                #pragma unroll
                for (int nt = 0; nt < 4; nt++) {
                    MMA16816(acc[mt][nt], ah[mt], fb_h[nt]);
                    MMA16816(acc[mt][nt], ah[mt], fb_l[nt]);
                    MMA16816(acc[mt][nt], al[mt], fb_h[nt]);
                }
        }

        if (c < 31) STORECH((c + 1) & 1);
        __syncthreads();
    }

    #pragma unroll
    for (int mt = 0; mt < 4; mt++) {
        #pragma unroll
        for (int nt = 0; nt < 4; nt++) {
            int n  = col0 + wn*32 + nt*8 + tid*2;
            float b0 = bias[n], b1 = bias[n+1];
            #pragma unroll
            for (int half = 0; half < 2; half++) {
                int m  = row0 + wm*64 + mt*16 + gid + half*8;
                float v0 = acc[mt][nt][half*2+0] + b0;
                float v1 = acc[mt][nt][half*2+1] + b1;
                float* op;
                if (heads) {
                    int bb = m >> 9, t = m & 511;
                    op = out + ((size_t)((bb*NHH + (n >> 6))*TT + t))*DHH + (n & 63);
                } else {
                    op = out + (size_t)m*CC + n;
                }
                op[0] = v0; op[1] = v1;
            }
        }
    }
    #undef LOADCH
    #undef STORECH
}

// ---------------------------------------------------------------------------
// Transpose [bh][t=512][d=64] -> [bh][d=64][t=512]  (used for V only now)
// ---------------------------------------------------------------------------
__global__ void trans_td(const float* __restrict__ in, float* __restrict__ out) {
    __shared__ float tile[32][33];
    const int bh = blockIdx.z;
    const int d0 = blockIdx.x * 32, t0 = blockIdx.y * 32;
    const float* ip = in  + (size_t)bh*TT*DHH;
    float*       op = out + (size_t)bh*DHH*TT;
    const int tx = threadIdx.x, ty = threadIdx.y;
    #pragma unroll
    for (int i = 0; i < 32; i += 8)
        tile[ty+i][tx] = ip[(size_t)(t0+ty+i)*DHH + d0 + tx];
    __syncthreads();
    #pragma unroll
    for (int i = 0; i < 32; i += 8)
        op[(size_t)(d0+ty+i)*TT + t0 + tx] = tile[tx][ty+i];
}

// ---------------------------------------------------------------------------
// mask[b][q][k] = fwd[b][q][k] * bwd[b][k][q]
// ---------------------------------------------------------------------------
__global__ void mask_prod(const float* __restrict__ fwd,
                          const float* __restrict__ bwd,
                          float* __restrict__ out) {
    __shared__ float tile[32][33];
    const int b  = blockIdx.z;
    const int x0 = blockIdx.x * 32, y0 = blockIdx.y * 32;
    const float* fp = fwd + (size_t)b*HWW*HWW;
    const float* bp = bwd + (size_t)b*HWW*HWW;
    float*       op = out + (size_t)b*HWW*HWW;
    const int tx = threadIdx.x, ty = threadIdx.y;
    #pragma unroll
    for (int i = 0; i < 32; i += 8)
        tile[ty+i][tx] = bp[(size_t)(y0+ty+i)*HWW + x0 + tx];
    __syncthreads();
    #pragma unroll
    for (int i = 0; i < 32; i += 8) {
        int q = x0 + ty + i;
        int k = y0 + tx;
        op[(size_t)q*HWW + k] = fp[(size_t)q*HWW + k] * tile[tx][ty+i];
    }
}

// ---------------------------------------------------------------------------
// Attention v3: tensor-core (mma.sync split-bf16) both phases.
// Block = (bh) x 64 q-rows, 8 warps.
//   S-phase:  4 chunks of 128 k-cols; warp tile 32x32; Q,K native [t][d]
//   softmax:  fp32, warp per 8 rows
//   PV-phase: 4 chunks of 128 t; warp tile 32x16; B = vT[d][t]
// SMEM: S fp32 64x516 = 132096 B, chunk area 69632 B -> 201728 B total
// ---------------------------------------------------------------------------
#define S_PAD    516
#define S_BYTES  (64*S_PAD*4)
#define QK_STR   72
#define PV_STR   136
#define ATTN_SMEM (S_BYTES + 69632)

__global__ __launch_bounds__(256, 1) void attn3(const float* __restrict__ q,
                                                const float* __restrict__ k,
                                                const float* __restrict__ vT,
                                                const float* __restrict__ maskp,
                                                float* __restrict__ y) {
    float* S = (float*)dynsm;
    char* cp = (char*)dynsm + S_BYTES;
    // S-phase layout
    __nv_bfloat16* Qhi = (__nv_bfloat16*)cp;          // 64 x 72
    __nv_bfloat16* Qlo = Qhi + 4608;
    __nv_bfloat16* Khi = Qlo + 4608;                  // 128 x 72
    __nv_bfloat16* Klo = Khi + 9216;
    // PV-phase layout (aliases same area)
    __nv_bfloat16* Phi = (__nv_bfloat16*)cp;          // 64 x 136
    __nv_bfloat16* Plo = Phi + 8704;
    __nv_bfloat16* Vhi = Plo + 8704;                  // 64 x 136
    __nv_bfloat16* Vlo = Vhi + 8704;

    const int bhid = blockIdx.x;
    const int b  = bhid >> 4;
    const int h  = bhid & 15;
    const int q0 = blockIdx.y * 64;
    const int lt   = threadIdx.x;
    const int w    = lt >> 5;
    const int lane = lt & 31;
    const int wm   = w & 1;          // 0..1
    const int wn   = w >> 1;         // 0..3
    const int gid  = lane >> 2;      // 0..7
    const int tid  = lane & 3;       // 0..3

    const float* qb  = q  + ((size_t)bhid*TT + q0)*DHH;
    const float* kb  = k  + (size_t)bhid*TT*DHH;
    const float* vTb = vT + (size_t)bhid*DHH*TT;
    const float* mb  = maskp + (size_t)b*HWW*HWW;

    // load + split Q tile (64x64)
    #pragma unroll
    for (int i = 0; i < 4; i++) {
        int idx = lt + 256*i;
        int row = idx >> 4, col4 = (idx & 15) * 4;
        float4 a = *(const float4*)&qb[(size_t)row*DHH + col4];
        split_store(Qhi + row*QK_STR + col4, Qlo + row*QK_STR + col4, a);
    }

    // ---- S-phase ----
    for (int nc = 0; nc < 4; nc++) {
        __syncthreads();
        #pragma unroll
        for (int i = 0; i < 8; i++) {
            int idx = lt + 256*i;
            int row = idx >> 4, col4 = (idx & 15) * 4;
            float4 a = *(const float4*)&kb[(size_t)(nc*128 + row)*DHH + col4];
            split_store(Khi + row*QK_STR + col4, Klo + row*QK_STR + col4, a);
        }
        __syncthreads();

        float acc[2][4][4];
        #pragma unroll
        for (int mt = 0; mt < 2; mt++)
            #pragma unroll
            for (int nt = 0; nt < 4; nt++)
                #pragma unroll
                for (int e = 0; e < 4; e++) acc[mt][nt][e] = 0.f;

        #pragma unroll
        for (int k16 = 0; k16 < 64; k16 += 16) {
            uint32_t fa_h[2][4], fa_l[2][4], fb_h[4][2], fb_l[4][2];
            #pragma unroll
            for (int mt = 0; mt < 2; mt++) {
                int r = wm*32 + mt*16 + gid;
                fa_h[mt][0] = *(const uint32_t*)(Qhi + r*QK_STR     + k16 + tid*2);
                fa_h[mt][1] = *(const uint32_t*)(Qhi + (r+8)*QK_STR + k16 + tid*2);
                fa_h[mt][2] = *(const uint32_t*)(Qhi + r*QK_STR     + k16 + 8 + tid*2);
                fa_h[mt][3] = *(const uint32_t*)(Qhi + (r+8)*QK_STR + k16 + 8 + tid*2);
                fa_l[mt][0] = *(const uint32_t*)(Qlo + r*QK_STR     + k16 + tid*2);
                fa_l[mt][1] = *(const uint32_t*)(Qlo + (r+8)*QK_STR + k16 + tid*2);
                fa_l[mt][2] = *(const uint32_t*)(Qlo + r*QK_STR     + k16 + 8 + tid*2);
                fa_l[mt][3] = *(const uint32_t*)(Qlo + (r+8)*QK_STR + k16 + 8 + tid*2);
            }
            #pragma unroll
            for (int nt = 0; nt < 4; nt++) {
                int n = wn*32 + nt*8 + gid;
                fb_h[nt][0] = *(const uint32_t*)(Khi + n*QK_STR + k16 + tid*2);
                fb_h[nt][1] = *(const uint32_t*)(Khi + n*QK_STR + k16 + 8 + tid*2);
                fb_l[nt][0] = *(const uint32_t*)(Klo + n*QK_STR + k16 + tid*2);
                fb_l[nt][1] = *(const uint32_t*)(Klo + n*QK_STR + k16 + 8 + tid*2);
            }
            #pragma unroll
            for (int mt = 0; mt < 2; mt++)
                #pragma unroll
                for (int nt = 0; nt < 4; nt++) {
                    MMA16816(acc[mt][nt], fa_h[mt], fb_h[nt]);
                    MMA16816(acc[mt][nt], fa_h[mt], fb_l[nt]);
                    MMA16816(acc[mt][nt], fa_l[mt], fb_h[nt]);
                }
        }

        // scale + mask + store S chunk
        const bool masked = (q0 < HWW) && (nc < 2);
        #pragma unroll
        for (int mt = 0; mt < 2; mt++) {
            #pragma unroll
            for (int nt = 0; nt < 4; nt++) {
                int ncol = wn*32 + nt*8 + tid*2;
                #pragma unroll
                for (int half = 0; half < 2; half++) {
                    int m = wm*32 + mt*16 + gid + half*8;
                    float v0 = acc[mt][nt][half*2+0] * 0.125f;
                    float v1 = acc[mt][nt][half*2+1] * 0.125f;
                    if (masked) {
                        const float* mrow = &mb[(size_t)(q0+m)*HWW + nc*128 + ncol];
                        v0 *= mrow[0];
                        v1 *= mrow[1];
                    }
                    float* Sp = &S[m*S_PAD + nc*128 + ncol];
                    Sp[0] = v0; Sp[1] = v1;
                }
            }
        }
    }
    __syncthreads();

    // ---- softmax: warp w owns rows w*8..w*8+7 ----
    {
        for (int rr = 0; rr < 8; rr++) {
            float* Sr = &S[(w*8 + rr)*S_PAD];
            float vals[16];
            float mx = -1e30f;
            #pragma unroll
            for (int i = 0; i < 16; i++) {
                vals[i] = Sr[i*32 + lane];
                mx = fmaxf(mx, vals[i]);
            }
            #pragma unroll
            for (int o = 16; o > 0; o >>= 1)
                mx = fmaxf(mx, __shfl_xor_sync(0xffffffffu, mx, o));
            float sum = 0.f;
            #pragma unroll
            for (int i = 0; i < 16; i++) {
                vals[i] = __expf(vals[i] - mx);
                sum += vals[i];
            }
            #pragma unroll
            for (int o = 16; o > 0; o >>= 1)
                sum += __shfl_xor_sync(0xffffffffu, sum, o);
            float inv = 1.f / sum;
            #pragma unroll
            for (int i = 0; i < 16; i++)
                Sr[i*32 + lane] = vals[i] * inv;
        }
    }

    // ---- PV-phase ----
    float oacc[2][2][4];
    #pragma unroll
    for (int mt = 0; mt < 2; mt++)
        #pragma unroll
        for (int nt = 0; nt < 2; nt++)
            #pragma unroll
            for (int e = 0; e < 4; e++) oacc[mt][nt][e] = 0.f;

    for (int tc = 0; tc < 4; tc++) {
        __syncthreads();
        #pragma unroll
        for (int i = 0; i < 8; i++) {
            int idx = lt + 256*i;
            int row = idx >> 5, col4 = (idx & 31) * 4;
            float4 a = *(const float4*)&S[row*S_PAD + tc*128 + col4];
            split_store(Phi + row*PV_STR + col4, Plo + row*PV_STR + col4, a);
        }
        #pragma unroll
        for (int i = 0; i < 8; i++) {
            int idx = lt + 256*i;
            int row = idx >> 5, col4 = (idx & 31) * 4;
            float4 a = *(const float4*)&vTb[(size_t)row*TT + tc*128 + col4];
            split_store(Vhi + row*PV_STR + col4, Vlo + row*PV_STR + col4, a);
        }
        __syncthreads();

        #pragma unroll
        for (int k16 = 0; k16 < 128; k16 += 16) {
            uint32_t fa_h[2][4], fa_l[2][4], fb_h[2][2], fb_l[2][2];
            #pragma unroll
            for (int mt = 0; mt < 2; mt++) {
                int r = wm*32 + mt*16 + gid;
                fa_h[mt][0] = *(const uint32_t*)(Phi + r*PV_STR     + k16 + tid*2);
                fa_h[mt][1] = *(const uint32_t*)(Phi + (r+8)*PV_STR + k16 + tid*2);
                fa_h[mt][2] = *(const uint32_t*)(Phi + r*PV_STR     + k16 + 8 + tid*2);
                fa_h[mt][3] = *(const uint32_t*)(Phi + (r+8)*PV_STR + k16 + 8 + tid*2);
                fa_l[mt][0] = *(const uint32_t*)(Plo + r*PV_STR     + k16 + tid*2);
                fa_l[mt][1] = *(const uint32_t*)(Plo + (r+8)*PV_STR + k16 + tid*2);
                fa_l[mt][2] = *(const uint32_t*)(Plo + r*PV_STR     + k16 + 8 + tid*2);
                fa_l[mt][3] = *(const uint32_t*)(Plo + (r+8)*PV_STR + k16 + 8 + tid*2);
            }
            #pragma unroll
            for (int nt = 0; nt < 2; nt++) {
                int n = wn*16 + nt*8 + gid;
                fb_h[nt][0] = *(const uint32_t*)(Vhi + n*PV_STR + k16 + tid*2);
                fb_h[nt][1] = *(const uint32_t*)(Vhi + n*PV_STR + k16 + 8 + tid*2);
                fb_l[nt][0] = *(const uint32_t*)(Vlo + n*PV_STR + k16 + tid*2);
                fb_l[nt][1] = *(const uint32_t*)(Vlo + n*PV_STR + k16 + 8 + tid*2);
            }
            #pragma unroll
            for (int mt = 0; mt < 2; mt++)
                #pragma unroll
                for (int nt = 0; nt < 2; nt++) {
                    MMA16816(oacc[mt][nt], fa_h[mt], fb_h[nt]);
                    MMA16816(oacc[mt][nt], fa_h[mt], fb_l[nt]);
                    MMA16816(oacc[mt][nt], fa_l[mt], fb_h[nt]);
                }
        }
    }

    // store O
    #pragma unroll
    for (int mt = 0; mt < 2; mt++) {
        #pragma unroll
        for (int nt = 0; nt < 2; nt++) {
            int d = wn*16 + nt*8 + tid*2;
            #pragma unroll
            for (int half = 0; half < 2; half++) {
                int m = q0 + wm*32 + mt*16 + gid + half*8;
                float* op = &y[(size_t)(b*TT + m)*CC + h*DHH + d];
                op[0] = oacc[mt][nt][half*2+0];
                op[1] = oacc[mt][nt][half*2+1];
            }
        }
    }
}

// ---------------------------------------------------------------------------
extern "C" void kernel_launch(void* const* d_in, const int* in_sizes, int n_in,
                              void* d_out, int out_size) {
    const float* x    = (const float*)d_in[0];
    const float* src  = (const float*)d_in[1];
    const float* fwd  = (const float*)d_in[2];
    const float* bwd  = (const float*)d_in[3];
    const float* Wq   = (const float*)d_in[4];
    const float* bq   = (const float*)d_in[5];
    const float* Wk   = (const float*)d_in[6];
    const float* bk   = (const float*)d_in[7];
    const float* Wv   = (const float*)d_in[8];
    const float* bv   = (const float*)d_in[9];
    const float* Wp   = (const float*)d_in[10];
    const float* bp   = (const float*)d_in[11];
    float* out = (float*)d_out;

    float *pq, *pk, *pv, *pvT, *pm, *py;
    cudaGetSymbolAddress((void**)&pq,  g_q);
    cudaGetSymbolAddress((void**)&pk,  g_k);
    cudaGetSymbolAddress((void**)&pv,  g_v);
    cudaGetSymbolAddress((void**)&pvT, g_vT);
    cudaGetSymbolAddress((void**)&pm,  g_mask);
    cudaGetSymbolAddress((void**)&py,  g_y);

    cudaFuncSetAttribute(gemm_mma, cudaFuncAttributeMaxDynamicSharedMemorySize, GEMM_SMEM);
    cudaFuncSetAttribute(attn3,    cudaFuncAttributeMaxDynamicSharedMemorySize, ATTN_SMEM);

    dim3 ggrid(CC/128, MM/128);      // (8, 32)
    gemm_mma<<<ggrid, 256, GEMM_SMEM>>>(x,   Wq, bq, pq, 1);
    gemm_mma<<<ggrid, 256, GEMM_SMEM>>>(src, Wk, bk, pk, 1);
    gemm_mma<<<ggrid, 256, GEMM_SMEM>>>(src, Wv, bv, pv, 1);

    dim3 tgrid(2, 16, BB*NHH);
    dim3 tblk(32, 8);
    trans_td<<<tgrid, tblk>>>(pv, pvT);

    dim3 mgrid(8, 8, BB);
    mask_prod<<<mgrid, tblk>>>(fwd, bwd, pm);

    dim3 agrid(BB*NHH, TT/64);       // (128, 8)
    attn3<<<agrid, 256, ATTN_SMEM>>>(pq, pk, pvT, pm, py);

    gemm_mma<<<ggrid, 256, GEMM_SMEM>>>(py, Wp, bp, out, 0);
}